// round 2
// baseline (speedup 1.0000x reference)
#include <cuda_runtime.h>
#include <cuda_bf16.h>

// Problem constants
#define BB   4
#define NN   10000
#define FF   128
#define UU   128
#define EE   160000
#define BN   (BB * NN)          // 40000

// ---------------- device scratch (no allocations allowed) ----------------
__device__ float g_h[BN * UU];       // relu(X @ W_t + b_t)
__device__ float g_scat[BN * UU];    // scattered attention aggregate
__device__ float g_asrc[BN];         // h . W_a[0:U]
__device__ float g_atgt[BN];         // h . W_a[U:2U]
__device__ float g_w[BB * EE];       // exp(att) per (b, e)
__device__ float g_expsum[1];        // global softmax denominator
__device__ int   g_deg[NN];
__device__ int   g_off[NN + 1];
__device__ int   g_cursor[NN];
__device__ int   g_csr[EE];          // edge ids sorted by src (bucketed)

// ---------------- helpers ----------------
union F2U { unsigned long long u; float2 f; };

__device__ __forceinline__ unsigned long long fma2(unsigned long long a,
                                                   unsigned long long b,
                                                   unsigned long long c) {
    unsigned long long d;
    asm("fma.rn.f32x2 %0, %1, %2, %3;" : "=l"(d) : "l"(a), "l"(b), "l"(c));
    return d;
}

// ---------------- K0: zero counters ----------------
__global__ void zero_kernel() {
    int tid = threadIdx.x;
    if (tid == 0) g_expsum[0] = 0.0f;
    for (int i = tid; i < NN; i += blockDim.x) g_deg[i] = 0;
}

// ---------------- K1: count degrees by src ----------------
// NOTE: edge_indices is INT32 (jax default x64-disabled downcasts int64).
__global__ void count_kernel(const int* __restrict__ edges) {
    int e = blockIdx.x * blockDim.x + threadIdx.x;
    if (e < EE) {
        int s = edges[2 * e];
        atomicAdd(&g_deg[s], 1);
    }
}

// ---------------- K2: transform  h = relu(X W_t + b_t), plus a_src/a_tgt ----
// Block: 256 threads = 4 groups of 64. Each group handles 4 nodes (NPT=4).
// 16 nodes per block, grid = 2500. W_t staged in smem; x duplicated as f32x2.
__global__ void __launch_bounds__(256) transform_kernel(
    const float* __restrict__ nf, const float* __restrict__ Wt,
    const float* __restrict__ bt, const float* __restrict__ Wa) {
    extern __shared__ float smem[];
    float*  Wt_s = smem;                            // 128*128 floats (64KB)
    float2* xd   = (float2*)(smem + FF * UU);       // [16][128] f32x2 (16KB)
    float*  red  = (float*)(xd + 16 * FF);          // 8 warps * 8 vals

    const int tid = threadIdx.x;
    const int g   = tid >> 6;        // group 0..3
    const int t   = tid & 63;        // thread in group
    const int wig = t >> 5;          // warp within group
    const int nb  = blockIdx.x * 16; // first flat node of block

    // stage W_t (float4)
    {
        const float4* srcp = (const float4*)Wt;
        float4* dstp = (float4*)Wt_s;
        for (int i = tid; i < (FF * UU) / 4; i += 256) dstp[i] = srcp[i];
    }
    // stage duplicated x for 16 nodes
    for (int i = tid; i < 16 * FF; i += 256) {
        int node = nb + (i >> 7);
        int k = i & 127;
        float v = nf[node * FF + k];
        xd[i] = make_float2(v, v);
    }
    __syncthreads();

    // group g handles nodes nb + 4g .. nb + 4g + 3
    const unsigned long long* xr =
        (const unsigned long long*)(xd + (g * 4) * FF);
    F2U a0, a1, a2, a3;
    a0.u = a1.u = a2.u = a3.u = 0ull;

#pragma unroll 16
    for (int k = 0; k < FF; k++) {
        unsigned long long w2 =
            *(const unsigned long long*)&Wt_s[k * UU + 2 * t];
        a0.u = fma2(xr[k],            w2, a0.u);
        a1.u = fma2(xr[FF + k],       w2, a1.u);
        a2.u = fma2(xr[2 * FF + k],   w2, a2.u);
        a3.u = fma2(xr[3 * FF + k],   w2, a3.u);
    }

    float b0 = bt[2 * t], b1 = bt[2 * t + 1];
    float wa_s0 = Wa[2 * t],        wa_s1 = Wa[2 * t + 1];
    float wa_t0 = Wa[UU + 2 * t],   wa_t1 = Wa[UU + 2 * t + 1];

    float ps[4], pt[4];
    F2U* accs[4] = {&a0, &a1, &a2, &a3};
#pragma unroll
    for (int j = 0; j < 4; j++) {
        float2 h = accs[j]->f;
        h.x = fmaxf(h.x + b0, 0.0f);
        h.y = fmaxf(h.y + b1, 0.0f);
        int node = nb + g * 4 + j;
        *(float2*)&g_h[node * UU + 2 * t] = h;
        ps[j] = h.x * wa_s0 + h.y * wa_s1;
        pt[j] = h.x * wa_t0 + h.y * wa_t1;
    }

    // warp reduce the 8 partials
#pragma unroll
    for (int o = 16; o > 0; o >>= 1) {
#pragma unroll
        for (int j = 0; j < 4; j++) {
            ps[j] += __shfl_down_sync(0xFFFFFFFFu, ps[j], o);
            pt[j] += __shfl_down_sync(0xFFFFFFFFu, pt[j], o);
        }
    }
    if ((t & 31) == 0) {
        float* r = red + (g * 2 + wig) * 8;
#pragma unroll
        for (int j = 0; j < 4; j++) { r[j] = ps[j]; r[4 + j] = pt[j]; }
    }
    __syncthreads();
    if (t == 0) {
        float* r0 = red + (g * 2) * 8;
        float* r1 = red + (g * 2 + 1) * 8;
#pragma unroll
        for (int j = 0; j < 4; j++) {
            int node = nb + g * 4 + j;
            g_asrc[node] = r0[j] + r1[j];
            g_atgt[node] = r0[4 + j] + r1[4 + j];
        }
    }
}

// ---------------- K3: exclusive scan of degrees (single block) ----------------
__global__ void __launch_bounds__(1024) scan_kernel() {
    __shared__ int s[1024];
    const int tid = threadIdx.x;
    const int base = tid * 10;
    int loc[10];
    int sum = 0;
#pragma unroll
    for (int j = 0; j < 10; j++) {
        int i = base + j;
        int v = (i < NN) ? g_deg[i] : 0;
        loc[j] = v;
        sum += v;
    }
    s[tid] = sum;
    __syncthreads();
    for (int o = 1; o < 1024; o <<= 1) {
        int v = (tid >= o) ? s[tid - o] : 0;
        __syncthreads();
        s[tid] += v;
        __syncthreads();
    }
    int run = s[tid] - sum;  // exclusive base
#pragma unroll
    for (int j = 0; j < 10; j++) {
        int i = base + j;
        if (i < NN) {
            g_off[i] = run;
            g_cursor[i] = run;
            run += loc[j];
        }
    }
    if (tid == 1023) g_off[NN] = s[1023];
}

// ---------------- K4: fill CSR buckets ----------------
__global__ void fill_kernel(const int* __restrict__ edges) {
    int e = blockIdx.x * blockDim.x + threadIdx.x;
    if (e < EE) {
        int s = edges[2 * e];
        int p = atomicAdd(&g_cursor[s], 1);
        g_csr[p] = e;
    }
}

// ---------------- K5: edge weights  exp(tanh(asrc+atgt+ba)) and global sum ----
__global__ void __launch_bounds__(256) edgew_kernel(
    const int* __restrict__ edges, const float* __restrict__ ba) {
    __shared__ float rs[256];
    int e = blockIdx.x * blockDim.x + threadIdx.x;
    float partial = 0.0f;
    float ba0 = ba[0];
    if (e < EE) {
        int s = edges[2 * e];
        int t = edges[2 * e + 1];
#pragma unroll
        for (int b = 0; b < BB; b++) {
            float att = tanhf(g_asrc[b * NN + s] + g_atgt[b * NN + t] + ba0);
            float ex = __expf(att);
            g_w[b * EE + e] = ex;
            partial += ex;
        }
    }
    rs[threadIdx.x] = partial;
    __syncthreads();
    for (int o = 128; o > 0; o >>= 1) {
        if (threadIdx.x < o) rs[threadIdx.x] += rs[threadIdx.x + o];
        __syncthreads();
    }
    if (threadIdx.x == 0) atomicAdd(g_expsum, rs[0]);
}

// ---------------- K6: aggregate  scat[b,n,:] = sum_e (w[b,e]/S) * h[b,tgt,:] --
// One warp per (b, n). Lane owns a float4 (4 channels).
__global__ void __launch_bounds__(256) agg_kernel(
    const int* __restrict__ edges) {
    int warp = (blockIdx.x * blockDim.x + threadIdx.x) >> 5;
    int lane = threadIdx.x & 31;
    if (warp >= BN) return;
    int b = warp / NN;
    int n = warp - b * NN;
    int o0 = g_off[n];
    int o1 = g_off[n + 1];
    float invS = 1.0f / g_expsum[0];
    const float4* hb = (const float4*)(g_h + (size_t)b * NN * UU);
    float4 acc = make_float4(0.f, 0.f, 0.f, 0.f);
    for (int j = o0; j < o1; j++) {
        int e = g_csr[j];
        int tgt = edges[2 * e + 1];
        float w = g_w[b * EE + e] * invS;
        float4 hv = hb[tgt * 32 + lane];
        acc.x += w * hv.x;
        acc.y += w * hv.y;
        acc.z += w * hv.z;
        acc.w += w * hv.w;
    }
    ((float4*)g_scat)[(size_t)warp * 32 + lane] = acc;
}

// ---------------- K7: output GEMM  out = relu([h, scat] W_c + b_c) ------------
// Block: 256 threads = 4 groups of 64. Each group handles 8 nodes (NPT=8).
// 32 nodes per block, grid = 1250. W_c (256x128, 128KB) in smem.
__global__ void __launch_bounds__(256) out_kernel(
    const float* __restrict__ Wc, const float* __restrict__ bc,
    float* __restrict__ out) {
    extern __shared__ float smem[];
    float*  Wc_s = smem;                         // 256*128 floats (128KB)
    float2* xd   = (float2*)(smem + 2 * UU * UU);  // [32][256] f32x2 (64KB)

    const int tid = threadIdx.x;
    const int g   = tid >> 6;
    const int t   = tid & 63;
    const int nb  = blockIdx.x * 32;

    // stage W_c
    {
        const float4* srcp = (const float4*)Wc;
        float4* dstp = (float4*)Wc_s;
        for (int i = tid; i < (2 * UU * UU) / 4; i += 256) dstp[i] = srcp[i];
    }
    // stage concat(h, scat) duplicated for 32 nodes
    for (int i = tid; i < 32 * 256; i += 256) {
        int node = nb + (i >> 8);
        int k = i & 255;
        float v = (k < UU) ? g_h[node * UU + k]
                           : g_scat[node * UU + (k - UU)];
        xd[i] = make_float2(v, v);
    }
    __syncthreads();

    const unsigned long long* xbase =
        (const unsigned long long*)(xd + (g * 8) * 256);
    F2U acc[8];
#pragma unroll
    for (int j = 0; j < 8; j++) acc[j].u = 0ull;

#pragma unroll 8
    for (int k = 0; k < 256; k++) {
        unsigned long long w2 =
            *(const unsigned long long*)&Wc_s[k * UU + 2 * t];
#pragma unroll
        for (int j = 0; j < 8; j++)
            acc[j].u = fma2(xbase[j * 256 + k], w2, acc[j].u);
    }

    float b0 = bc[2 * t], b1 = bc[2 * t + 1];
#pragma unroll
    for (int j = 0; j < 8; j++) {
        int node = nb + g * 8 + j;
        float2 r = acc[j].f;
        r.x = fmaxf(r.x + b0, 0.0f);
        r.y = fmaxf(r.y + b1, 0.0f);
        *(float2*)&out[node * UU + 2 * t] = r;
    }
}

// ---------------- launch ----------------
extern "C" void kernel_launch(void* const* d_in, const int* in_sizes, int n_in,
                              void* d_out, int out_size) {
    const float* nf    = (const float*)d_in[0];
    const int*   edges = (const int*)d_in[1];   // int32! (jax x64 disabled)
    const float* Wt    = (const float*)d_in[2];
    const float* bt    = (const float*)d_in[3];
    const float* Wa    = (const float*)d_in[4];
    const float* ba    = (const float*)d_in[5];
    const float* Wc    = (const float*)d_in[6];
    const float* bc    = (const float*)d_in[7];
    float*       out   = (float*)d_out;

    const int SMEM_T = FF * UU * 4 + 16 * FF * 8 + 64 * 4;     // ~82KB
    const int SMEM_O = 2 * UU * UU * 4 + 32 * 256 * 8;         // 192KB

    cudaFuncSetAttribute(transform_kernel,
                         cudaFuncAttributeMaxDynamicSharedMemorySize, SMEM_T);
    cudaFuncSetAttribute(out_kernel,
                         cudaFuncAttributeMaxDynamicSharedMemorySize, SMEM_O);

    zero_kernel<<<1, 1024>>>();
    count_kernel<<<(EE + 255) / 256, 256>>>(edges);
    transform_kernel<<<BN / 16, 256, SMEM_T>>>(nf, Wt, bt, Wa);
    scan_kernel<<<1, 1024>>>();
    fill_kernel<<<(EE + 255) / 256, 256>>>(edges);
    edgew_kernel<<<(EE + 255) / 256, 256>>>(edges, ba);
    agg_kernel<<<BN / 8, 256>>>(edges);
    out_kernel<<<BN / 32, 256, SMEM_O>>>(Wc, bc, out);
}

// round 5
// speedup vs baseline: 1.6043x; 1.6043x over previous
#include <cuda_runtime.h>
#include <cuda_bf16.h>
#include <cstdint>

// Problem constants
#define BB   4
#define NN   10000
#define FF   128
#define UU   128
#define EE   160000
#define BN   (BB * NN)          // 40000

// ---------------- device scratch ----------------
__device__ float  g_h[BN * UU];        // relu(X @ W_t + b_t), [b*NN+n][128]
__device__ float  g_scat[BN * UU];     // aggregated, same layout
__device__ float  g_asrc[NN * 4];      // [n][b] h . W_a[0:U]
__device__ float  g_atgt[NN * 4];      // [n][b] h . W_a[U:2U]
__device__ float4 g_w4[EE];            // [e][b] exp(att)
__device__ float  g_expsum[1];
__device__ int    g_deg[NN];
__device__ int    g_off[NN + 1];
__device__ int    g_cursor[NN];
__device__ int    g_csr[EE];

// ---------------- helpers ----------------
__device__ __forceinline__ uint32_t smem_u32(const void* p) {
    uint32_t a;
    asm("{ .reg .u64 t; cvta.to.shared.u64 t, %1; cvt.u32.u64 %0, t; }"
        : "=r"(a) : "l"(p));
    return a;
}
__device__ __forceinline__ unsigned long long fma2(unsigned long long a,
                                                   unsigned long long b,
                                                   unsigned long long c) {
    unsigned long long d;
    asm("fma.rn.f32x2 %0, %1, %2, %3;" : "=l"(d) : "l"(a), "l"(b), "l"(c));
    return d;
}
__device__ __forceinline__ unsigned long long dup32(float x) {
    unsigned long long d;
    asm("mov.b64 %0, {%1, %1};" : "=l"(d) : "f"(x));
    return d;
}
__device__ __forceinline__ void unpack64(unsigned long long v, float& lo, float& hi) {
    asm("mov.b64 {%0, %1}, %2;" : "=f"(lo), "=f"(hi) : "l"(v));
}
__device__ __forceinline__ void ld_w2(uint32_t addr, unsigned long long& a,
                                      unsigned long long& b) {
    asm("ld.shared.v2.b64 {%0, %1}, [%2];" : "=l"(a), "=l"(b) : "r"(addr));
}

// ---------------- K0: zero ----------------
__global__ void zero_kernel() {
    int i = blockIdx.x * blockDim.x + threadIdx.x;
    if (i == 0) g_expsum[0] = 0.0f;
    if (i < NN) g_deg[i] = 0;
}

// ---------------- K1: count degrees by src (edges are int32) ----------------
__global__ void count_kernel(const int* __restrict__ edges) {
    int e = blockIdx.x * blockDim.x + threadIdx.x;
    if (e < EE) atomicAdd(&g_deg[edges[2 * e]], 1);
}

// ---------------- K2: transform  h = relu(X W_t + b_t) + a_src/a_tgt --------
// 256 threads = 8 warps; warp owns 8 nodes x 128 cols (4 cols/lane).
// 64 nodes/block, grid = 625. FMA2-pipe-bound inner loop.
__global__ void __launch_bounds__(256) transform_kernel(
    const float* __restrict__ nf, const float* __restrict__ Wt,
    const float* __restrict__ bt, const float* __restrict__ Wa) {
    extern __shared__ float sm[];
    float* Ws   = sm;                    // [128][128]
    float* xs   = sm + 16384;            // [64][128]
    float* bias = sm + 16384 + 8192;     // [128]
    float* waS  = bias + 128;
    float* waT  = bias + 256;

    const int tid  = threadIdx.x;
    const int lane = tid & 31;
    const int wrp  = tid >> 5;
    const int nb   = blockIdx.x * 64;

    // stage W_t (row k = input feature, col = output unit)
    {
        const float4* s4 = (const float4*)Wt;
        float4* d4 = (float4*)Ws;
        for (int i = tid; i < 4096; i += 256) d4[i] = s4[i];
    }
    // stage x rows
    {
        float4* d4 = (float4*)xs;
        for (int i = tid; i < 2048; i += 256) {
            int row = i >> 5, c4 = i & 31;
            d4[i] = *(const float4*)(nf + (size_t)(nb + row) * 128 + c4 * 4);
        }
    }
    if (tid < 128) { bias[tid] = bt[tid]; waS[tid] = Wa[tid]; waT[tid] = Wa[128 + tid]; }
    __syncthreads();

    const uint32_t wbase = smem_u32(Ws) + 16 * lane;
    const float4*  xsv   = (const float4*)(xs + (wrp * 8) * 128);

    unsigned long long acc[8][2];
#pragma unroll
    for (int n = 0; n < 8; n++) acc[n][0] = acc[n][1] = 0ull;

    for (int k4 = 0; k4 < 32; k4++) {
        unsigned long long w01[4], w23[4];
#pragma unroll
        for (int kk = 0; kk < 4; kk++)
            ld_w2(wbase + (k4 * 4 + kk) * 512, w01[kk], w23[kk]);
        float4 xv[8];
#pragma unroll
        for (int n = 0; n < 8; n++) xv[n] = xsv[n * 32 + k4];
#pragma unroll
        for (int kk = 0; kk < 4; kk++) {
#pragma unroll
            for (int n = 0; n < 8; n++) {
                float xk = (kk == 0) ? xv[n].x : (kk == 1) ? xv[n].y
                          : (kk == 2) ? xv[n].z : xv[n].w;
                unsigned long long xd = dup32(xk);
                acc[n][0] = fma2(xd, w01[kk], acc[n][0]);
                acc[n][1] = fma2(xd, w23[kk], acc[n][1]);
            }
        }
    }

    float4 bi = *(float4*)(bias + 4 * lane);
    float4 ws4 = *(float4*)(waS + 4 * lane);
    float4 wt4 = *(float4*)(waT + 4 * lane);

#pragma unroll
    for (int n = 0; n < 8; n++) {
        int node = nb + wrp * 8 + n;
        float h0, h1, h2, h3;
        unpack64(acc[n][0], h0, h1);
        unpack64(acc[n][1], h2, h3);
        h0 = fmaxf(h0 + bi.x, 0.f); h1 = fmaxf(h1 + bi.y, 0.f);
        h2 = fmaxf(h2 + bi.z, 0.f); h3 = fmaxf(h3 + bi.w, 0.f);
        *(float4*)(g_h + (size_t)node * 128 + 4 * lane) =
            make_float4(h0, h1, h2, h3);
        float as = h0 * ws4.x + h1 * ws4.y + h2 * ws4.z + h3 * ws4.w;
        float at = h0 * wt4.x + h1 * wt4.y + h2 * wt4.z + h3 * wt4.w;
#pragma unroll
        for (int o = 16; o > 0; o >>= 1) {
            as += __shfl_xor_sync(0xFFFFFFFFu, as, o);
            at += __shfl_xor_sync(0xFFFFFFFFu, at, o);
        }
        if (lane == 0) {
            int b = node / NN, nm = node - b * NN;
            g_asrc[nm * 4 + b] = as;
            g_atgt[nm * 4 + b] = at;
        }
    }
}

// ---------------- K3: scan (coalesced, warp-scan) ----------------
__global__ void __launch_bounds__(1024) scan_kernel() {
    __shared__ int sdeg[10240];
    __shared__ int warpsums[32];
    const int tid = threadIdx.x, lane = tid & 31, wrp = tid >> 5;
    for (int i = tid; i < 10240; i += 1024) sdeg[i] = (i < NN) ? g_deg[i] : 0;
    __syncthreads();
    int loc[10], sum = 0;
#pragma unroll
    for (int j = 0; j < 10; j++) { int v = sdeg[tid * 10 + j]; loc[j] = v; sum += v; }
    int inc = sum;
#pragma unroll
    for (int o = 1; o < 32; o <<= 1) {
        int n = __shfl_up_sync(0xFFFFFFFFu, inc, o);
        if (lane >= o) inc += n;
    }
    if (lane == 31) warpsums[wrp] = inc;
    __syncthreads();
    if (wrp == 0) {
        int w = warpsums[lane];
#pragma unroll
        for (int o = 1; o < 32; o <<= 1) {
            int n = __shfl_up_sync(0xFFFFFFFFu, w, o);
            if (lane >= o) w += n;
        }
        warpsums[lane] = w;
    }
    __syncthreads();
    int run = (wrp ? warpsums[wrp - 1] : 0) + inc - sum;
#pragma unroll
    for (int j = 0; j < 10; j++) { sdeg[tid * 10 + j] = run; run += loc[j]; }
    __syncthreads();
    for (int i = tid; i < NN; i += 1024) {
        int v = sdeg[i];
        g_off[i] = v;
        g_cursor[i] = v;
    }
    if (tid == 1023) g_off[NN] = warpsums[31];
}

// ---------------- K4: fill CSR ----------------
__global__ void fill_kernel(const int* __restrict__ edges) {
    int e = blockIdx.x * blockDim.x + threadIdx.x;
    if (e < EE) {
        int s = edges[2 * e];
        int p = atomicAdd(&g_cursor[s], 1);
        g_csr[p] = e;
    }
}

// ---------------- K5: edge weights  exp(tanh(asrc+atgt+ba)), global sum -----
__global__ void __launch_bounds__(256) edgew_kernel(
    const int* __restrict__ edges, const float* __restrict__ ba) {
    __shared__ float rs[256];
    int e = blockIdx.x * blockDim.x + threadIdx.x;
    float partial = 0.0f;
    float ba0 = ba[0];
    if (e < EE) {
        int s = edges[2 * e];
        int t = edges[2 * e + 1];
        float4 as4 = *(const float4*)(g_asrc + s * 4);
        float4 at4 = *(const float4*)(g_atgt + t * 4);
        float z[4] = {as4.x + at4.x, as4.y + at4.y, as4.z + at4.z, as4.w + at4.w};
        float4 w;
        float* wp = (float*)&w;
#pragma unroll
        for (int b = 0; b < 4; b++) {
            float zz = z[b] + ba0;
            float att = 1.0f - __fdividef(2.0f, __expf(2.0f * zz) + 1.0f);
            float ex = __expf(att);
            wp[b] = ex;
            partial += ex;
        }
        g_w4[e] = w;
    }
    rs[threadIdx.x] = partial;
    __syncthreads();
    for (int o = 128; o > 0; o >>= 1) {
        if (threadIdx.x < o) rs[threadIdx.x] += rs[threadIdx.x + o];
        __syncthreads();
    }
    if (threadIdx.x == 0) atomicAdd(g_expsum, rs[0]);
}

// ---------------- K6: aggregate. One warp per node, all 4 batches -----------
__global__ void __launch_bounds__(256) agg_kernel(const int* __restrict__ edges) {
    int n = blockIdx.x * 8 + (threadIdx.x >> 5);
    int lane = threadIdx.x & 31;
    if (n >= NN) return;
    int o0 = g_off[n];
    int o1 = g_off[n + 1];
    float invS = 1.0f / g_expsum[0];
    const float4* hb = (const float4*)g_h;
    float4 a0 = make_float4(0.f, 0.f, 0.f, 0.f), a1 = a0, a2 = a0, a3 = a0;
    for (int j = o0; j < o1; j++) {
        int e = g_csr[j];
        int tgt = edges[2 * e + 1];
        float4 w = g_w4[e];
        float4 h0 = hb[(size_t)(0 * NN + tgt) * 32 + lane];
        float4 h1 = hb[(size_t)(1 * NN + tgt) * 32 + lane];
        float4 h2 = hb[(size_t)(2 * NN + tgt) * 32 + lane];
        float4 h3 = hb[(size_t)(3 * NN + tgt) * 32 + lane];
        a0.x += w.x * h0.x; a0.y += w.x * h0.y; a0.z += w.x * h0.z; a0.w += w.x * h0.w;
        a1.x += w.y * h1.x; a1.y += w.y * h1.y; a1.z += w.y * h1.z; a1.w += w.y * h1.w;
        a2.x += w.z * h2.x; a2.y += w.z * h2.y; a2.z += w.z * h2.z; a2.w += w.z * h2.w;
        a3.x += w.w * h3.x; a3.y += w.w * h3.y; a3.z += w.w * h3.z; a3.w += w.w * h3.w;
    }
    a0.x *= invS; a0.y *= invS; a0.z *= invS; a0.w *= invS;
    a1.x *= invS; a1.y *= invS; a1.z *= invS; a1.w *= invS;
    a2.x *= invS; a2.y *= invS; a2.z *= invS; a2.w *= invS;
    a3.x *= invS; a3.y *= invS; a3.z *= invS; a3.w *= invS;
    float4* sc = (float4*)g_scat;
    sc[(size_t)(0 * NN + n) * 32 + lane] = a0;
    sc[(size_t)(1 * NN + n) * 32 + lane] = a1;
    sc[(size_t)(2 * NN + n) * 32 + lane] = a2;
    sc[(size_t)(3 * NN + n) * 32 + lane] = a3;
}

// ---------------- K7: output GEMM  out = relu([h, scat] W_c + b_c) ----------
// Same structure as transform, K=256.
__global__ void __launch_bounds__(256) out_kernel(
    const float* __restrict__ Wc, const float* __restrict__ bc,
    float* __restrict__ out) {
    extern __shared__ float sm[];
    float* Ws   = sm;                 // [256][128]
    float* xs   = sm + 32768;         // [64][256]
    float* bias = sm + 32768 + 16384; // [128]

    const int tid  = threadIdx.x;
    const int lane = tid & 31;
    const int wrp  = tid >> 5;
    const int nb   = blockIdx.x * 64;

    {
        const float4* s4 = (const float4*)Wc;
        float4* d4 = (float4*)Ws;
        for (int i = tid; i < 8192; i += 256) d4[i] = s4[i];
    }
    {
        float4* d4 = (float4*)xs;
        for (int i = tid; i < 4096; i += 256) {
            int row = i >> 6, c4 = i & 63;
            float4 v;
            if (c4 < 32)
                v = *(const float4*)(g_h + (size_t)(nb + row) * 128 + c4 * 4);
            else
                v = *(const float4*)(g_scat + (size_t)(nb + row) * 128 + (c4 - 32) * 4);
            d4[i] = v;
        }
    }
    if (tid < 128) bias[tid] = bc[tid];
    __syncthreads();

    const uint32_t wbase = smem_u32(Ws) + 16 * lane;
    const float4*  xsv   = (const float4*)(xs + (wrp * 8) * 256);

    unsigned long long acc[8][2];
#pragma unroll
    for (int n = 0; n < 8; n++) acc[n][0] = acc[n][1] = 0ull;

    for (int k4 = 0; k4 < 64; k4++) {
        unsigned long long w01[4], w23[4];
#pragma unroll
        for (int kk = 0; kk < 4; kk++)
            ld_w2(wbase + (k4 * 4 + kk) * 512, w01[kk], w23[kk]);
        float4 xv[8];
#pragma unroll
        for (int n = 0; n < 8; n++) xv[n] = xsv[n * 64 + k4];
#pragma unroll
        for (int kk = 0; kk < 4; kk++) {
#pragma unroll
            for (int n = 0; n < 8; n++) {
                float xk = (kk == 0) ? xv[n].x : (kk == 1) ? xv[n].y
                          : (kk == 2) ? xv[n].z : xv[n].w;
                unsigned long long xd = dup32(xk);
                acc[n][0] = fma2(xd, w01[kk], acc[n][0]);
                acc[n][1] = fma2(xd, w23[kk], acc[n][1]);
            }
        }
    }

    float4 bi = *(float4*)(bias + 4 * lane);
#pragma unroll
    for (int n = 0; n < 8; n++) {
        int node = nb + wrp * 8 + n;
        float h0, h1, h2, h3;
        unpack64(acc[n][0], h0, h1);
        unpack64(acc[n][1], h2, h3);
        h0 = fmaxf(h0 + bi.x, 0.f); h1 = fmaxf(h1 + bi.y, 0.f);
        h2 = fmaxf(h2 + bi.z, 0.f); h3 = fmaxf(h3 + bi.w, 0.f);
        *(float4*)(out + (size_t)node * 128 + 4 * lane) =
            make_float4(h0, h1, h2, h3);
    }
}

// ---------------- launch ----------------
extern "C" void kernel_launch(void* const* d_in, const int* in_sizes, int n_in,
                              void* d_out, int out_size) {
    const float* nf    = (const float*)d_in[0];
    const int*   edges = (const int*)d_in[1];   // int32 (jax x64 disabled)
    const float* Wt    = (const float*)d_in[2];
    const float* bt    = (const float*)d_in[3];
    const float* Wa    = (const float*)d_in[4];
    const float* ba    = (const float*)d_in[5];
    const float* Wc    = (const float*)d_in[6];
    const float* bc    = (const float*)d_in[7];
    float*       out   = (float*)d_out;

    const int SMEM_T = (16384 + 8192 + 384) * 4;      // ~97.5KB
    const int SMEM_O = (32768 + 16384 + 128) * 4;     // ~192.5KB

    cudaFuncSetAttribute(transform_kernel,
                         cudaFuncAttributeMaxDynamicSharedMemorySize, SMEM_T);
    cudaFuncSetAttribute(out_kernel,
                         cudaFuncAttributeMaxDynamicSharedMemorySize, SMEM_O);

    zero_kernel<<<40, 256>>>();
    count_kernel<<<(EE + 255) / 256, 256>>>(edges);
    transform_kernel<<<BN / 64, 256, SMEM_T>>>(nf, Wt, bt, Wa);
    scan_kernel<<<1, 1024>>>();
    fill_kernel<<<(EE + 255) / 256, 256>>>(edges);
    edgew_kernel<<<(EE + 255) / 256, 256>>>(edges, ba);
    agg_kernel<<<(NN + 7) / 8, 256>>>(edges);
    out_kernel<<<BN / 64, 256, SMEM_O>>>(Wc, bc, out);
}

// round 8
// speedup vs baseline: 1.6811x; 1.0479x over previous
#include <cuda_runtime.h>
#include <cuda_bf16.h>
#include <cstdint>

// Problem constants
#define BB   4
#define NN   10000
#define FF   128
#define UU   128
#define EE   160000
#define BN   (BB * NN)          // 40000
#define CAP  96                 // per-node CSR bucket capacity (mean deg 16)

// ---------------- device scratch ----------------
__device__ float  g_h[BN * UU];        // relu(X @ W_t + b_t), [b*NN+n][128]
__device__ float  g_scat[BN * UU];     // aggregated, same layout
__device__ float  g_asrc[NN * 4];      // [n][b] h . W_a[0:U]
__device__ float  g_atgt[NN * 4];      // [n][b] h . W_a[U:2U]
__device__ float4 g_w4[EE];            // [e][b] exp(att)
__device__ float  g_expsum[1];
__device__ int    g_cursor[NN];
__device__ unsigned int g_csr[NN * CAP];  // packed (e<<14)|tgt  (UNSIGNED: e is 18 bits)

// ---------------- helpers ----------------
__device__ __forceinline__ uint32_t smem_u32(const void* p) {
    uint32_t a;
    asm("{ .reg .u64 t; cvta.to.shared.u64 t, %1; cvt.u32.u64 %0, t; }"
        : "=r"(a) : "l"(p));
    return a;
}
__device__ __forceinline__ unsigned long long fma2(unsigned long long a,
                                                   unsigned long long b,
                                                   unsigned long long c) {
    unsigned long long d;
    asm("fma.rn.f32x2 %0, %1, %2, %3;" : "=l"(d) : "l"(a), "l"(b), "l"(c));
    return d;
}
__device__ __forceinline__ unsigned long long dup32(float x) {
    unsigned long long d;
    asm("mov.b64 %0, {%1, %1};" : "=l"(d) : "f"(x));
    return d;
}
__device__ __forceinline__ void unpack64(unsigned long long v, float& lo, float& hi) {
    asm("mov.b64 {%0, %1}, %2;" : "=f"(lo), "=f"(hi) : "l"(v));
}
__device__ __forceinline__ void ld_w2(uint32_t addr, unsigned long long& a,
                                      unsigned long long& b) {
    asm("ld.shared.v2.b64 {%0, %1}, [%2];" : "=l"(a), "=l"(b) : "r"(addr));
}
// exp(x) on [-1,1], degree-7 Taylor (max rel err ~2.5e-5); keeps MUFU free
__device__ __forceinline__ float exp_poly(float x) {
    float p = 1.98412698e-4f;
    p = fmaf(p, x, 1.38888889e-3f);
    p = fmaf(p, x, 8.33333333e-3f);
    p = fmaf(p, x, 4.16666667e-2f);
    p = fmaf(p, x, 1.66666667e-1f);
    p = fmaf(p, x, 0.5f);
    p = fmaf(p, x, 1.0f);
    p = fmaf(p, x, 1.0f);
    return p;
}

// ---------------- K0: zero ----------------
__global__ void zero_kernel() {
    int i = blockIdx.x * blockDim.x + threadIdx.x;
    if (i == 0) g_expsum[0] = 0.0f;
    if (i < NN) g_cursor[i] = 0;
}

// ---------------- K1: fill bucketed CSR (edges are int32) ----------------
__global__ void fill_kernel(const int* __restrict__ edges) {
    int e = blockIdx.x * blockDim.x + threadIdx.x;
    if (e < EE) {
        int s = edges[2 * e];
        int t = edges[2 * e + 1];
        int p = atomicAdd(&g_cursor[s], 1);
        if (p < CAP)
            g_csr[s * CAP + p] = ((unsigned int)e << 14) | (unsigned int)t;
    }
}

// ---------------- K2: transform  h = relu(X W_t + b_t) + a_src/a_tgt --------
// 256 threads = 8 warps; warp owns 8 nodes x 128 cols (4 cols/lane).
__global__ void __launch_bounds__(256) transform_kernel(
    const float* __restrict__ nf, const float* __restrict__ Wt,
    const float* __restrict__ bt, const float* __restrict__ Wa) {
    extern __shared__ float sm[];
    float* Ws   = sm;                    // [128][128]
    float* xs   = sm + 16384;            // [64][128]
    float* bias = sm + 16384 + 8192;     // [128]
    float* waS  = bias + 128;
    float* waT  = bias + 256;

    const int tid  = threadIdx.x;
    const int lane = tid & 31;
    const int wrp  = tid >> 5;
    const int nb   = blockIdx.x * 64;

    {
        const float4* s4 = (const float4*)Wt;
        float4* d4 = (float4*)Ws;
        for (int i = tid; i < 4096; i += 256) d4[i] = s4[i];
    }
    {
        float4* d4 = (float4*)xs;
        for (int i = tid; i < 2048; i += 256) {
            int row = i >> 5, c4 = i & 31;
            d4[i] = *(const float4*)(nf + (size_t)(nb + row) * 128 + c4 * 4);
        }
    }
    if (tid < 128) { bias[tid] = bt[tid]; waS[tid] = Wa[tid]; waT[tid] = Wa[128 + tid]; }
    __syncthreads();

    const uint32_t wbase = smem_u32(Ws) + 16 * lane;
    const float4*  xsv   = (const float4*)(xs + (wrp * 8) * 128);

    unsigned long long acc[8][2];
#pragma unroll
    for (int n = 0; n < 8; n++) acc[n][0] = acc[n][1] = 0ull;

    for (int k4 = 0; k4 < 32; k4++) {
        unsigned long long w01[4], w23[4];
#pragma unroll
        for (int kk = 0; kk < 4; kk++)
            ld_w2(wbase + (k4 * 4 + kk) * 512, w01[kk], w23[kk]);
        float4 xv[8];
#pragma unroll
        for (int n = 0; n < 8; n++) xv[n] = xsv[n * 32 + k4];
#pragma unroll
        for (int kk = 0; kk < 4; kk++) {
#pragma unroll
            for (int n = 0; n < 8; n++) {
                float xk = (kk == 0) ? xv[n].x : (kk == 1) ? xv[n].y
                          : (kk == 2) ? xv[n].z : xv[n].w;
                unsigned long long xd = dup32(xk);
                acc[n][0] = fma2(xd, w01[kk], acc[n][0]);
                acc[n][1] = fma2(xd, w23[kk], acc[n][1]);
            }
        }
    }

    float4 bi  = *(float4*)(bias + 4 * lane);
    float4 ws4 = *(float4*)(waS + 4 * lane);
    float4 wt4 = *(float4*)(waT + 4 * lane);

#pragma unroll
    for (int n = 0; n < 8; n++) {
        int node = nb + wrp * 8 + n;
        float h0, h1, h2, h3;
        unpack64(acc[n][0], h0, h1);
        unpack64(acc[n][1], h2, h3);
        h0 = fmaxf(h0 + bi.x, 0.f); h1 = fmaxf(h1 + bi.y, 0.f);
        h2 = fmaxf(h2 + bi.z, 0.f); h3 = fmaxf(h3 + bi.w, 0.f);
        *(float4*)(g_h + (size_t)node * 128 + 4 * lane) =
            make_float4(h0, h1, h2, h3);
        float as = h0 * ws4.x + h1 * ws4.y + h2 * ws4.z + h3 * ws4.w;
        float at = h0 * wt4.x + h1 * wt4.y + h2 * wt4.z + h3 * wt4.w;
#pragma unroll
        for (int o = 16; o > 0; o >>= 1) {
            as += __shfl_xor_sync(0xFFFFFFFFu, as, o);
            at += __shfl_xor_sync(0xFFFFFFFFu, at, o);
        }
        if (lane == 0) {
            int b = node / NN, nm = node - b * NN;
            g_asrc[nm * 4 + b] = as;
            g_atgt[nm * 4 + b] = at;
        }
    }
}

// ---------------- K3: edge weights  exp(tanh(asrc+atgt+ba)), global sum -----
__global__ void __launch_bounds__(256) edgew_kernel(
    const int* __restrict__ edges, const float* __restrict__ ba) {
    int e = blockIdx.x * blockDim.x + threadIdx.x;
    float partial = 0.0f;
    float ba0 = ba[0];
    if (e < EE) {
        int s = edges[2 * e];
        int t = edges[2 * e + 1];
        float4 as4 = *(const float4*)(g_asrc + s * 4);
        float4 at4 = *(const float4*)(g_atgt + t * 4);
        float z[4] = {as4.x + at4.x, as4.y + at4.y, as4.z + at4.z, as4.w + at4.w};
        float4 w;
        float* wp = (float*)&w;
#pragma unroll
        for (int b = 0; b < 4; b++) {
            float zz = z[b] + ba0;
            float att = 1.0f - __fdividef(2.0f, __expf(2.0f * zz) + 1.0f);
            float ex = exp_poly(att);   // att in [-1,1]
            wp[b] = ex;
            partial += ex;
        }
        g_w4[e] = w;
    }
#pragma unroll
    for (int o = 16; o > 0; o >>= 1)
        partial += __shfl_xor_sync(0xFFFFFFFFu, partial, o);
    if ((threadIdx.x & 31) == 0) atomicAdd(g_expsum, partial);
}

// ---------------- K4: aggregate. One warp per node, all 4 batches -----------
__global__ void __launch_bounds__(256) agg_kernel() {
    int n = blockIdx.x * 8 + (threadIdx.x >> 5);
    int lane = threadIdx.x & 31;
    if (n >= NN) return;
    int cnt = g_cursor[n];
    if (cnt > CAP) cnt = CAP;
    float invS = 1.0f / g_expsum[0];
    const float4* hb = (const float4*)g_h;
    const unsigned int* bucket = g_csr + n * CAP;
    float4 a0 = make_float4(0.f, 0.f, 0.f, 0.f), a1 = a0, a2 = a0, a3 = a0;
    for (int j = 0; j < cnt; j++) {
        unsigned int v = bucket[j];
        int e = (int)(v >> 14);
        int tgt = (int)(v & 0x3FFFu);
        float4 w = g_w4[e];
        float4 h0 = hb[(size_t)(0 * NN + tgt) * 32 + lane];
        float4 h1 = hb[(size_t)(1 * NN + tgt) * 32 + lane];
        float4 h2 = hb[(size_t)(2 * NN + tgt) * 32 + lane];
        float4 h3 = hb[(size_t)(3 * NN + tgt) * 32 + lane];
        a0.x += w.x * h0.x; a0.y += w.x * h0.y; a0.z += w.x * h0.z; a0.w += w.x * h0.w;
        a1.x += w.y * h1.x; a1.y += w.y * h1.y; a1.z += w.y * h1.z; a1.w += w.y * h1.w;
        a2.x += w.z * h2.x; a2.y += w.z * h2.y; a2.z += w.z * h2.z; a2.w += w.z * h2.w;
        a3.x += w.w * h3.x; a3.y += w.w * h3.y; a3.z += w.w * h3.z; a3.w += w.w * h3.w;
    }
    a0.x *= invS; a0.y *= invS; a0.z *= invS; a0.w *= invS;
    a1.x *= invS; a1.y *= invS; a1.z *= invS; a1.w *= invS;
    a2.x *= invS; a2.y *= invS; a2.z *= invS; a2.w *= invS;
    a3.x *= invS; a3.y *= invS; a3.z *= invS; a3.w *= invS;
    float4* sc = (float4*)g_scat;
    sc[(size_t)(0 * NN + n) * 32 + lane] = a0;
    sc[(size_t)(1 * NN + n) * 32 + lane] = a1;
    sc[(size_t)(2 * NN + n) * 32 + lane] = a2;
    sc[(size_t)(3 * NN + n) * 32 + lane] = a3;
}

// ---------------- K5: output GEMM  out = relu([h, scat] W_c + b_c) ----------
__global__ void __launch_bounds__(256) out_kernel(
    const float* __restrict__ Wc, const float* __restrict__ bc,
    float* __restrict__ out) {
    extern __shared__ float sm[];
    float* Ws   = sm;                 // [256][128]
    float* xs   = sm + 32768;         // [64][256]
    float* bias = sm + 32768 + 16384; // [128]

    const int tid  = threadIdx.x;
    const int lane = tid & 31;
    const int wrp  = tid >> 5;
    const int nb   = blockIdx.x * 64;

    {
        const float4* s4 = (const float4*)Wc;
        float4* d4 = (float4*)Ws;
        for (int i = tid; i < 8192; i += 256) d4[i] = s4[i];
    }
    {
        float4* d4 = (float4*)xs;
        for (int i = tid; i < 4096; i += 256) {
            int row = i >> 6, c4 = i & 63;
            float4 v;
            if (c4 < 32)
                v = *(const float4*)(g_h + (size_t)(nb + row) * 128 + c4 * 4);
            else
                v = *(const float4*)(g_scat + (size_t)(nb + row) * 128 + (c4 - 32) * 4);
            d4[i] = v;
        }
    }
    if (tid < 128) bias[tid] = bc[tid];
    __syncthreads();

    const uint32_t wbase = smem_u32(Ws) + 16 * lane;
    const float4*  xsv   = (const float4*)(xs + (wrp * 8) * 256);

    unsigned long long acc[8][2];
#pragma unroll
    for (int n = 0; n < 8; n++) acc[n][0] = acc[n][1] = 0ull;

    for (int k4 = 0; k4 < 64; k4++) {
        unsigned long long w01[4], w23[4];
#pragma unroll
        for (int kk = 0; kk < 4; kk++)
            ld_w2(wbase + (k4 * 4 + kk) * 512, w01[kk], w23[kk]);
        float4 xv[8];
#pragma unroll
        for (int n = 0; n < 8; n++) xv[n] = xsv[n * 64 + k4];
#pragma unroll
        for (int kk = 0; kk < 4; kk++) {
#pragma unroll
            for (int n = 0; n < 8; n++) {
                float xk = (kk == 0) ? xv[n].x : (kk == 1) ? xv[n].y
                          : (kk == 2) ? xv[n].z : xv[n].w;
                unsigned long long xd = dup32(xk);
                acc[n][0] = fma2(xd, w01[kk], acc[n][0]);
                acc[n][1] = fma2(xd, w23[kk], acc[n][1]);
            }
        }
    }

    float4 bi = *(float4*)(bias + 4 * lane);
#pragma unroll
    for (int n = 0; n < 8; n++) {
        int node = nb + wrp * 8 + n;
        float h0, h1, h2, h3;
        unpack64(acc[n][0], h0, h1);
        unpack64(acc[n][1], h2, h3);
        h0 = fmaxf(h0 + bi.x, 0.f); h1 = fmaxf(h1 + bi.y, 0.f);
        h2 = fmaxf(h2 + bi.z, 0.f); h3 = fmaxf(h3 + bi.w, 0.f);
        *(float4*)(out + (size_t)node * 128 + 4 * lane) =
            make_float4(h0, h1, h2, h3);
    }
}

// ---------------- launch ----------------
extern "C" void kernel_launch(void* const* d_in, const int* in_sizes, int n_in,
                              void* d_out, int out_size) {
    const float* nf    = (const float*)d_in[0];
    const int*   edges = (const int*)d_in[1];   // int32 (jax x64 disabled)
    const float* Wt    = (const float*)d_in[2];
    const float* bt    = (const float*)d_in[3];
    const float* Wa    = (const float*)d_in[4];
    const float* ba    = (const float*)d_in[5];
    const float* Wc    = (const float*)d_in[6];
    const float* bc    = (const float*)d_in[7];
    float*       out   = (float*)d_out;

    const int SMEM_T = (16384 + 8192 + 384) * 4;      // ~97.5KB
    const int SMEM_O = (32768 + 16384 + 128) * 4;     // ~192.5KB

    cudaFuncSetAttribute(transform_kernel,
                         cudaFuncAttributeMaxDynamicSharedMemorySize, SMEM_T);
    cudaFuncSetAttribute(out_kernel,
                         cudaFuncAttributeMaxDynamicSharedMemorySize, SMEM_O);

    zero_kernel<<<40, 256>>>();
    fill_kernel<<<(EE + 255) / 256, 256>>>(edges);
    transform_kernel<<<BN / 64, 256, SMEM_T>>>(nf, Wt, bt, Wa);
    edgew_kernel<<<(EE + 255) / 256, 256>>>(edges, ba);
    agg_kernel<<<(NN + 7) / 8, 256>>>();
    out_kernel<<<BN / 64, 256, SMEM_O>>>(Wc, bc, out);
}

// round 9
// speedup vs baseline: 1.8263x; 1.0864x over previous
#include <cuda_runtime.h>
#include <cuda_bf16.h>
#include <cstdint>

// Problem constants
#define BB   4
#define NN   10000
#define EE   160000
#define BN   40000
#define CAP  96

// ---------------- device scratch ----------------
__device__ float  g_h[BN * 128];
__device__ float  g_scat[BN * 128];
__device__ float  g_asrc[NN * 4];      // [n][b], accumulated via atomics
__device__ float  g_atgt[NN * 4];
__device__ float4 g_w4[EE];
__device__ float  g_expsum[1];
__device__ int    g_cursor[NN];
__device__ unsigned int g_csr[NN * CAP];   // packed (e<<14)|tgt (e is 18 bits)

// ---------------- helpers ----------------
__device__ __forceinline__ void mma16816(float* d, const uint32_t* a,
                                         const uint32_t* b) {
    asm volatile(
        "mma.sync.aligned.m16n8k16.row.col.f32.bf16.bf16.f32 "
        "{%0,%1,%2,%3}, {%4,%5,%6,%7}, {%8,%9}, {%0,%1,%2,%3};"
        : "+f"(d[0]), "+f"(d[1]), "+f"(d[2]), "+f"(d[3])
        : "r"(a[0]), "r"(a[1]), "r"(a[2]), "r"(a[3]), "r"(b[0]), "r"(b[1]));
}
__device__ __forceinline__ void split_bf16(float v, uint16_t& h, uint16_t& l) {
    __nv_bfloat16 hb = __float2bfloat16(v);
    __nv_bfloat16 lb = __float2bfloat16(v - __bfloat162float(hb));
    h = *(uint16_t*)&hb;
    l = *(uint16_t*)&lb;
}
__device__ __forceinline__ void split_pack2(float x, float y, uint32_t& hi,
                                            uint32_t& lo) {
    uint16_t hx, lx, hy, ly;
    split_bf16(x, hx, lx);
    split_bf16(y, hy, ly);
    hi = (uint32_t)hx | ((uint32_t)hy << 16);
    lo = (uint32_t)lx | ((uint32_t)ly << 16);
}
// exp(x) on [-1,1], degree-7 Taylor; keeps MUFU free
__device__ __forceinline__ float exp_poly(float x) {
    float p = 1.98412698e-4f;
    p = fmaf(p, x, 1.38888889e-3f);
    p = fmaf(p, x, 8.33333333e-3f);
    p = fmaf(p, x, 4.16666667e-2f);
    p = fmaf(p, x, 1.66666667e-1f);
    p = fmaf(p, x, 0.5f);
    p = fmaf(p, x, 1.0f);
    p = fmaf(p, x, 1.0f);
    return p;
}

// ---------------- K0: zero ----------------
__global__ void zero_kernel() {
    int i = blockIdx.x * blockDim.x + threadIdx.x;
    if (i == 0) g_expsum[0] = 0.0f;
    if (i < NN) g_cursor[i] = 0;
    if (i < NN * 4) { g_asrc[i] = 0.0f; g_atgt[i] = 0.0f; }
}

// ---------------- K1: fill bucketed CSR (edges int32) ----------------
__global__ void fill_kernel(const int* __restrict__ edges) {
    int e = blockIdx.x * blockDim.x + threadIdx.x;
    if (e < EE) {
        int2 st = *(const int2*)(edges + 2 * e);
        int p = atomicAdd(&g_cursor[st.x], 1);
        if (p < CAP)
            g_csr[st.x * CAP + p] = ((unsigned int)e << 14) | (unsigned int)st.y;
    }
}

// ======================= transform (tensor core) =======================
// block: 256 thr = 8 warps = 4 M-groups(16 nodes) x 2 N-halves(64 cols).
// A = node_features (bf16 hi/lo), B = Wt^T (bf16 hi/lo). K=128.
#define TPA 68          // A row pitch in u32 words (136 bf16 elems)
#define TPB 136         // B row pitch in bf16 elems (=68 words)
#define T_BH   0
#define T_BL   34816
#define T_AH   69632
#define T_AL   87040
#define T_BIAS 104448
#define T_WAS  104960
#define T_WAT  105472
#define T_SMEM 105984

__global__ void __launch_bounds__(256) transform_mma(
    const float* __restrict__ nf, const float* __restrict__ Wt,
    const float* __restrict__ bt, const float* __restrict__ Wa) {
    extern __shared__ char sm[];
    uint16_t* BH = (uint16_t*)(sm + T_BH);
    uint16_t* BL = (uint16_t*)(sm + T_BL);
    uint32_t* AH = (uint32_t*)(sm + T_AH);
    uint32_t* AL = (uint32_t*)(sm + T_AL);
    float* bias = (float*)(sm + T_BIAS);
    float* waS  = (float*)(sm + T_WAS);
    float* waT  = (float*)(sm + T_WAT);

    const int tid = threadIdx.x, lane = tid & 31, w = tid >> 5;
    const int nb = blockIdx.x * 64;

    // stage B: Wt[k=128][n=128] fp32 -> WT[n][k] bf16 hi/lo
    for (int i = tid; i < 16384; i += 256) {
        int k = i >> 7, n = i & 127;
        uint16_t h, l;
        split_bf16(Wt[i], h, l);
        BH[n * TPB + k] = h;
        BL[n * TPB + k] = l;
    }
    // stage A: 64 node rows, bf16 hi/lo packed pairs
    for (int i = tid; i < 2048; i += 256) {
        int node = i >> 5, c4 = i & 31;
        float4 v = *(const float4*)(nf + (size_t)(nb + node) * 128 + c4 * 4);
        uint32_t h01, l01, h23, l23;
        split_pack2(v.x, v.y, h01, l01);
        split_pack2(v.z, v.w, h23, l23);
        int widx = node * TPA + c4 * 2;
        AH[widx] = h01; AH[widx + 1] = h23;
        AL[widx] = l01; AL[widx + 1] = l23;
    }
    if (tid < 128) { bias[tid] = bt[tid]; waS[tid] = Wa[tid]; waT[tid] = Wa[128 + tid]; }
    __syncthreads();

    const int g = lane >> 2, t = lane & 3;
    const int mg = w >> 1, nh = w & 1;
    const int nbase = nh * 64;

    float D[8][4];
#pragma unroll
    for (int nt = 0; nt < 8; nt++)
#pragma unroll
        for (int j = 0; j < 4; j++) D[nt][j] = 0.0f;

    const uint32_t arow0 = (mg * 16 + g) * TPA;
    const uint32_t arow1 = arow0 + 8 * TPA;

#pragma unroll
    for (int ks = 0; ks < 8; ks++) {
        const int kw = ks * 8 + t;   // word offset within row: kb/2 + t
        uint32_t ah[4], al[4];
        ah[0] = AH[arow0 + kw];     ah[1] = AH[arow1 + kw];
        ah[2] = AH[arow0 + kw + 4]; ah[3] = AH[arow1 + kw + 4];
        al[0] = AL[arow0 + kw];     al[1] = AL[arow1 + kw];
        al[2] = AL[arow0 + kw + 4]; al[3] = AL[arow1 + kw + 4];
#pragma unroll
        for (int nt = 0; nt < 8; nt++) {
            int n = nbase + nt * 8 + g;
            const uint32_t* bhp = (const uint32_t*)(BH + n * TPB);
            const uint32_t* blp = (const uint32_t*)(BL + n * TPB);
            uint32_t bh[2], bl[2];
            bh[0] = bhp[kw]; bh[1] = bhp[kw + 4];
            bl[0] = blp[kw]; bl[1] = blp[kw + 4];
            mma16816(D[nt], ah, bh);
            mma16816(D[nt], ah, bl);
            mma16816(D[nt], al, bh);
        }
    }

    // epilogue: relu + bias, store h, partial attention dots
    const int node0 = nb + mg * 16 + g;
    const int node1 = node0 + 8;
    float pS0 = 0.f, pS1 = 0.f, pT0 = 0.f, pT1 = 0.f;
#pragma unroll
    for (int nt = 0; nt < 8; nt++) {
        int c = nbase + nt * 8 + 2 * t;
        float b0 = bias[c], b1 = bias[c + 1];
        float h00 = fmaxf(D[nt][0] + b0, 0.f), h01 = fmaxf(D[nt][1] + b1, 0.f);
        float h10 = fmaxf(D[nt][2] + b0, 0.f), h11 = fmaxf(D[nt][3] + b1, 0.f);
        *(float2*)(g_h + (size_t)node0 * 128 + c) = make_float2(h00, h01);
        *(float2*)(g_h + (size_t)node1 * 128 + c) = make_float2(h10, h11);
        float s0 = waS[c], s1 = waS[c + 1], t0 = waT[c], t1 = waT[c + 1];
        pS0 += h00 * s0 + h01 * s1;  pS1 += h10 * s0 + h11 * s1;
        pT0 += h00 * t0 + h01 * t1;  pT1 += h10 * t0 + h11 * t1;
    }
    pS0 += __shfl_xor_sync(0xFFFFFFFFu, pS0, 1); pS0 += __shfl_xor_sync(0xFFFFFFFFu, pS0, 2);
    pS1 += __shfl_xor_sync(0xFFFFFFFFu, pS1, 1); pS1 += __shfl_xor_sync(0xFFFFFFFFu, pS1, 2);
    pT0 += __shfl_xor_sync(0xFFFFFFFFu, pT0, 1); pT0 += __shfl_xor_sync(0xFFFFFFFFu, pT0, 2);
    pT1 += __shfl_xor_sync(0xFFFFFFFFu, pT1, 1); pT1 += __shfl_xor_sync(0xFFFFFFFFu, pT1, 2);
    if (t == 0) {
        int b0i = node0 / NN, n0 = node0 - b0i * NN;
        atomicAdd(&g_asrc[n0 * 4 + b0i], pS0);
        atomicAdd(&g_atgt[n0 * 4 + b0i], pT0);
        int b1i = node1 / NN, n1 = node1 - b1i * NN;
        atomicAdd(&g_asrc[n1 * 4 + b1i], pS1);
        atomicAdd(&g_atgt[n1 * 4 + b1i], pT1);
    }
}

// ---------------- K3: edge weights, 2 edges/thread ----------------
__global__ void __launch_bounds__(256) edgew_kernel(
    const int* __restrict__ edges, const float* __restrict__ ba) {
    int base = (blockIdx.x * blockDim.x + threadIdx.x) * 2;
    float partial = 0.0f;
    float ba0 = ba[0];
    if (base < EE) {   // EE even, base even -> base+1 < EE too
        int4 e4 = *(const int4*)(edges + 2 * base);
        float4 as0 = *(const float4*)(g_asrc + e4.x * 4);
        float4 at0 = *(const float4*)(g_atgt + e4.y * 4);
        float4 as1 = *(const float4*)(g_asrc + e4.z * 4);
        float4 at1 = *(const float4*)(g_atgt + e4.w * 4);
        float z0[4] = {as0.x + at0.x, as0.y + at0.y, as0.z + at0.z, as0.w + at0.w};
        float z1[4] = {as1.x + at1.x, as1.y + at1.y, as1.z + at1.z, as1.w + at1.w};
        float4 w0, w1;
        float* wp0 = (float*)&w0;
        float* wp1 = (float*)&w1;
#pragma unroll
        for (int b = 0; b < 4; b++) {
            float a0 = 1.0f - __fdividef(2.0f, __expf(2.0f * (z0[b] + ba0)) + 1.0f);
            float a1 = 1.0f - __fdividef(2.0f, __expf(2.0f * (z1[b] + ba0)) + 1.0f);
            float e0 = exp_poly(a0), e1 = exp_poly(a1);
            wp0[b] = e0; wp1[b] = e1;
            partial += e0 + e1;
        }
        g_w4[base] = w0;
        g_w4[base + 1] = w1;
    }
#pragma unroll
    for (int o = 16; o > 0; o >>= 1)
        partial += __shfl_xor_sync(0xFFFFFFFFu, partial, o);
    if ((threadIdx.x & 31) == 0) atomicAdd(g_expsum, partial);
}

// ---------------- K4: aggregate. One warp per node, all 4 batches ----------
__global__ void __launch_bounds__(256) agg_kernel() {
    int n = blockIdx.x * 8 + (threadIdx.x >> 5);
    int lane = threadIdx.x & 31;
    if (n >= NN) return;
    int cnt = g_cursor[n];
    if (cnt > CAP) cnt = CAP;
    float invS = 1.0f / g_expsum[0];
    const float4* hb = (const float4*)g_h;
    const unsigned int* bucket = g_csr + n * CAP;
    float4 a0 = make_float4(0.f, 0.f, 0.f, 0.f), a1 = a0, a2 = a0, a3 = a0;
    for (int j = 0; j < cnt; j++) {
        unsigned int v = bucket[j];
        int e = (int)(v >> 14);
        int tgt = (int)(v & 0x3FFFu);
        float4 w = g_w4[e];
        float4 h0 = hb[(size_t)(0 * NN + tgt) * 32 + lane];
        float4 h1 = hb[(size_t)(1 * NN + tgt) * 32 + lane];
        float4 h2 = hb[(size_t)(2 * NN + tgt) * 32 + lane];
        float4 h3 = hb[(size_t)(3 * NN + tgt) * 32 + lane];
        a0.x += w.x * h0.x; a0.y += w.x * h0.y; a0.z += w.x * h0.z; a0.w += w.x * h0.w;
        a1.x += w.y * h1.x; a1.y += w.y * h1.y; a1.z += w.y * h1.z; a1.w += w.y * h1.w;
        a2.x += w.z * h2.x; a2.y += w.z * h2.y; a2.z += w.z * h2.z; a2.w += w.z * h2.w;
        a3.x += w.w * h3.x; a3.y += w.w * h3.y; a3.z += w.w * h3.z; a3.w += w.w * h3.w;
    }
    a0.x *= invS; a0.y *= invS; a0.z *= invS; a0.w *= invS;
    a1.x *= invS; a1.y *= invS; a1.z *= invS; a1.w *= invS;
    a2.x *= invS; a2.y *= invS; a2.z *= invS; a2.w *= invS;
    a3.x *= invS; a3.y *= invS; a3.z *= invS; a3.w *= invS;
    float4* sc = (float4*)g_scat;
    sc[(size_t)(0 * NN + n) * 32 + lane] = a0;
    sc[(size_t)(1 * NN + n) * 32 + lane] = a1;
    sc[(size_t)(2 * NN + n) * 32 + lane] = a2;
    sc[(size_t)(3 * NN + n) * 32 + lane] = a3;
}

// ======================= output GEMM (tensor core) =======================
// K=256 ([h, scat]), same warp layout as transform.
#define OPA 132         // A row pitch in u32 words (264 bf16 elems)
#define OPB 264         // B row pitch in bf16 elems (=132 words)
#define O_BH   0
#define O_BL   67584
#define O_AH   135168
#define O_AL   168960
#define O_BIAS 202752
#define O_SMEM 203264

__global__ void __launch_bounds__(256) out_mma(
    const float* __restrict__ Wc, const float* __restrict__ bc,
    float* __restrict__ out) {
    extern __shared__ char sm[];
    uint16_t* BH = (uint16_t*)(sm + O_BH);
    uint16_t* BL = (uint16_t*)(sm + O_BL);
    uint32_t* AH = (uint32_t*)(sm + O_AH);
    uint32_t* AL = (uint32_t*)(sm + O_AL);
    float* bias = (float*)(sm + O_BIAS);

    const int tid = threadIdx.x, lane = tid & 31, w = tid >> 5;
    const int nb = blockIdx.x * 64;

    // stage B: Wc[k=256][n=128] -> WT[n][k] bf16 hi/lo
    for (int i = tid; i < 32768; i += 256) {
        int k = i >> 7, n = i & 127;
        uint16_t h, l;
        split_bf16(Wc[i], h, l);
        BH[n * OPB + k] = h;
        BL[n * OPB + k] = l;
    }
    // stage A: 64 rows of [h(128) | scat(128)]
    for (int i = tid; i < 4096; i += 256) {
        int node = i >> 6, c4 = i & 63;
        float4 v;
        if (c4 < 32)
            v = *(const float4*)(g_h + (size_t)(nb + node) * 128 + c4 * 4);
        else
            v = *(const float4*)(g_scat + (size_t)(nb + node) * 128 + (c4 - 32) * 4);
        uint32_t h01, l01, h23, l23;
        split_pack2(v.x, v.y, h01, l01);
        split_pack2(v.z, v.w, h23, l23);
        int widx = node * OPA + c4 * 2;
        AH[widx] = h01; AH[widx + 1] = h23;
        AL[widx] = l01; AL[widx + 1] = l23;
    }
    if (tid < 128) bias[tid] = bc[tid];
    __syncthreads();

    const int g = lane >> 2, t = lane & 3;
    const int mg = w >> 1, nh = w & 1;
    const int nbase = nh * 64;

    float D[8][4];
#pragma unroll
    for (int nt = 0; nt < 8; nt++)
#pragma unroll
        for (int j = 0; j < 4; j++) D[nt][j] = 0.0f;

    const uint32_t arow0 = (mg * 16 + g) * OPA;
    const uint32_t arow1 = arow0 + 8 * OPA;

#pragma unroll
    for (int ks = 0; ks < 16; ks++) {
        const int kw = ks * 8 + t;
        uint32_t ah[4], al[4];
        ah[0] = AH[arow0 + kw];     ah[1] = AH[arow1 + kw];
        ah[2] = AH[arow0 + kw + 4]; ah[3] = AH[arow1 + kw + 4];
        al[0] = AL[arow0 + kw];     al[1] = AL[arow1 + kw];
        al[2] = AL[arow0 + kw + 4]; al[3] = AL[arow1 + kw + 4];
#pragma unroll
        for (int nt = 0; nt < 8; nt++) {
            int n = nbase + nt * 8 + g;
            const uint32_t* bhp = (const uint32_t*)(BH + n * OPB);
            const uint32_t* blp = (const uint32_t*)(BL + n * OPB);
            uint32_t bh[2], bl[2];
            bh[0] = bhp[kw]; bh[1] = bhp[kw + 4];
            bl[0] = blp[kw]; bl[1] = blp[kw + 4];
            mma16816(D[nt], ah, bh);
            mma16816(D[nt], ah, bl);
            mma16816(D[nt], al, bh);
        }
    }

    const int node0 = nb + mg * 16 + g;
    const int node1 = node0 + 8;
#pragma unroll
    for (int nt = 0; nt < 8; nt++) {
        int c = nbase + nt * 8 + 2 * t;
        float b0 = bias[c], b1 = bias[c + 1];
        float h00 = fmaxf(D[nt][0] + b0, 0.f), h01 = fmaxf(D[nt][1] + b1, 0.f);
        float h10 = fmaxf(D[nt][2] + b0, 0.f), h11 = fmaxf(D[nt][3] + b1, 0.f);
        *(float2*)(out + (size_t)node0 * 128 + c) = make_float2(h00, h01);
        *(float2*)(out + (size_t)node1 * 128 + c) = make_float2(h10, h11);
    }
}

// ---------------- launch ----------------
extern "C" void kernel_launch(void* const* d_in, const int* in_sizes, int n_in,
                              void* d_out, int out_size) {
    const float* nf    = (const float*)d_in[0];
    const int*   edges = (const int*)d_in[1];   // int32 (jax x64 disabled)
    const float* Wt    = (const float*)d_in[2];
    const float* bt    = (const float*)d_in[3];
    const float* Wa    = (const float*)d_in[4];
    const float* ba    = (const float*)d_in[5];
    const float* Wc    = (const float*)d_in[6];
    const float* bc    = (const float*)d_in[7];
    float*       out   = (float*)d_out;

    cudaFuncSetAttribute(transform_mma,
                         cudaFuncAttributeMaxDynamicSharedMemorySize, T_SMEM);
    cudaFuncSetAttribute(out_mma,
                         cudaFuncAttributeMaxDynamicSharedMemorySize, O_SMEM);

    zero_kernel<<<(NN * 4 + 255) / 256, 256>>>();
    fill_kernel<<<(EE + 255) / 256, 256>>>(edges);
    transform_mma<<<BN / 64, 256, T_SMEM>>>(nf, Wt, bt, Wa);
    edgew_kernel<<<(EE / 2 + 255) / 256, 256>>>(edges, ba);
    agg_kernel<<<(NN + 7) / 8, 256>>>();
    out_mma<<<BN / 64, 256, O_SMEM>>>(Wc, bc, out);
}